// round 8
// baseline (speedup 1.0000x reference)
#include <cuda_runtime.h>
#include <math.h>
#include <stdint.h>

// ---------------------------------------------------------------------------
// Problem constants
// ---------------------------------------------------------------------------
#define BB     8
#define HH     32
#define WW     32
#define NC     384
#define GROUPS 6
#define HEADS  12
#define HC     32
#define GC     64
#define NPIX   (HH*WW)          // 1024
#define MTOT   (BB*NPIX)        // 8192
#define NCH    12               // K chunks of 32

// ---------------------------------------------------------------------------
// Scratch (static device globals — no allocation allowed)
// ---------------------------------------------------------------------------
__device__ float g_q  [MTOT*NC];
__device__ float g_t  [MTOT*NC];
__device__ float g_xs [MTOT*NC];
__device__ float g_k  [MTOT*NC];
__device__ float g_v  [MTOT*NC];
__device__ float g_o  [MTOT*NC];

// ---------------------------------------------------------------------------
// mma.sync / packed-f32x2 helpers (base sm_103 ISA — NOT tcgen05)
// ---------------------------------------------------------------------------
__device__ __forceinline__ uint32_t f2tf32(float x) {
    uint32_t r;
    asm("cvt.rna.tf32.f32 %0, %1;" : "=r"(r) : "f"(x));
    return r;
}
__device__ __forceinline__ float ex2f(float x) {
    float r;
    asm("ex2.approx.f32 %0, %1;" : "=f"(r) : "f"(x));
    return r;
}
__device__ __forceinline__ void mma_tf32(float* c, const uint32_t* a, const uint32_t* b) {
    asm volatile(
        "mma.sync.aligned.m16n8k8.row.col.f32.tf32.tf32.f32 "
        "{%0,%1,%2,%3}, {%4,%5,%6,%7}, {%8,%9}, {%0,%1,%2,%3};"
        : "+f"(c[0]), "+f"(c[1]), "+f"(c[2]), "+f"(c[3])
        : "r"(a[0]), "r"(a[1]), "r"(a[2]), "r"(a[3]), "r"(b[0]), "r"(b[1]));
}
#define FMA2(d, a, b) \
    asm("fma.rn.f32x2 %0, %1, %2, %0;" : "+l"(d) : "l"(a), "l"(b))
__device__ __forceinline__ uint64_t packf2(float lo, float hi) {
    uint64_t r;
    asm("mov.b64 %0, {%1, %2};" : "=l"(r) : "f"(lo), "f"(hi));
    return r;
}
__device__ __forceinline__ float2 unpackf2(uint64_t v) {
    float2 r;
    asm("mov.b64 {%0, %1}, %2;" : "=f"(r.x), "=f"(r.y) : "l"(v));
    return r;
}

// single dynamic-smem symbol for the whole TU
extern __shared__ uint32_t dynsm[];

// ---------------------------------------------------------------------------
// Pipelined tf32 mma GEMM: 512 thr, 16 warps (8m x 2n), warp tile 16x64,
// double-buffered smem + register prefetch, ONE sync per K-chunk.
// ---------------------------------------------------------------------------
#define GSA 36    // As row stride (u32)
#define GSB 136   // Bs row stride (u32)
#define GEMM_SMEM ((2*128*GSA + 2*32*GSB) * 4)

__device__ __forceinline__ void gemm_body_v2(
    const float* __restrict__ A, const float* __restrict__ W,
    const float* __restrict__ bias, float* __restrict__ C, uint32_t* sm)
{
    uint32_t* As = sm;                    // [2][128*GSA]
    uint32_t* Bs = sm + 2 * 128 * GSA;    // [2][32*GSB]
    const int tid = threadIdx.x, lane = tid & 31, wid = tid >> 5;
    const int wm = wid & 7, wn = wid >> 3;
    const int bm = blockIdx.x * 128, bn = blockIdx.y * 128;
    const int lq = lane >> 2, lr = lane & 3;

    float acc[8][4];
    #pragma unroll
    for (int j = 0; j < 8; j++)
        #pragma unroll
        for (int t = 0; t < 4; t++) acc[j][t] = 0.f;

    // prologue: stage chunk 0 into buffer 0
    #pragma unroll
    for (int l = 0; l < 2; l++) {
        int idx = tid + l * 512;
        float4 va = *reinterpret_cast<const float4*>(
            &A[(size_t)(bm + (idx >> 3)) * NC + (idx & 7) * 4]);
        uint32_t* d = &As[(idx >> 3) * GSA + (idx & 7) * 4];
        d[0] = f2tf32(va.x); d[1] = f2tf32(va.y);
        d[2] = f2tf32(va.z); d[3] = f2tf32(va.w);
        float4 vb = *reinterpret_cast<const float4*>(
            &W[(size_t)(idx >> 5) * NC + bn + (idx & 31) * 4]);
        uint32_t* e = &Bs[(idx >> 5) * GSB + (idx & 31) * 4];
        e[0] = f2tf32(vb.x); e[1] = f2tf32(vb.y);
        e[2] = f2tf32(vb.z); e[3] = f2tf32(vb.w);
    }
    __syncthreads();

    for (int c = 0; c < NCH; c++) {
        const int buf = c & 1;
        const bool more = (c + 1 < NCH);
        float4 pa[2], pb[2];
        if (more) {
            #pragma unroll
            for (int l = 0; l < 2; l++) {
                int idx = tid + l * 512;
                pa[l] = *reinterpret_cast<const float4*>(
                    &A[(size_t)(bm + (idx >> 3)) * NC + (c + 1) * 32 + (idx & 7) * 4]);
                pb[l] = *reinterpret_cast<const float4*>(
                    &W[(size_t)((c + 1) * 32 + (idx >> 5)) * NC + bn + (idx & 31) * 4]);
            }
        }
        const uint32_t* Ab = As + buf * 128 * GSA;
        const uint32_t* Bb = Bs + buf * 32 * GSB;
        #pragma unroll
        for (int ks = 0; ks < 4; ks++) {
            const int k0 = ks * 8;
            uint32_t af[4];
            const int rb = wm * 16;
            af[0] = Ab[(rb +     lq) * GSA + k0 +     lr];
            af[1] = Ab[(rb + 8 + lq) * GSA + k0 +     lr];
            af[2] = Ab[(rb +     lq) * GSA + k0 + 4 + lr];
            af[3] = Ab[(rb + 8 + lq) * GSA + k0 + 4 + lr];
            #pragma unroll
            for (int j = 0; j < 8; j++) {
                uint32_t bf[2];
                const int col = wn * 64 + j * 8 + lq;
                bf[0] = Bb[(k0 +     lr) * GSB + col];
                bf[1] = Bb[(k0 + 4 + lr) * GSB + col];
                mma_tf32(acc[j], af, bf);
            }
        }
        if (more) {
            uint32_t* Ad = As + (buf ^ 1) * 128 * GSA;
            uint32_t* Bd = Bs + (buf ^ 1) * 32 * GSB;
            #pragma unroll
            for (int l = 0; l < 2; l++) {
                int idx = tid + l * 512;
                uint32_t* d = &Ad[(idx >> 3) * GSA + (idx & 7) * 4];
                d[0] = f2tf32(pa[l].x); d[1] = f2tf32(pa[l].y);
                d[2] = f2tf32(pa[l].z); d[3] = f2tf32(pa[l].w);
                uint32_t* e = &Bd[(idx >> 5) * GSB + (idx & 31) * 4];
                e[0] = f2tf32(pb[l].x); e[1] = f2tf32(pb[l].y);
                e[2] = f2tf32(pb[l].z); e[3] = f2tf32(pb[l].w);
            }
        }
        __syncthreads();
    }

    #pragma unroll
    for (int j = 0; j < 8; j++) {
        const int col = bn + wn * 64 + j * 8 + lr * 2;
        const float b0 = bias[col], b1 = bias[col + 1];
        const int r0 = bm + wm * 16 + lq;
        *reinterpret_cast<float2*>(&C[(size_t)r0 * NC + col]) =
            make_float2(acc[j][0] + b0, acc[j][1] + b1);
        *reinterpret_cast<float2*>(&C[(size_t)(r0 + 8) * NC + col]) =
            make_float2(acc[j][2] + b0, acc[j][3] + b1);
    }
}

__global__ __launch_bounds__(512) void gemm_mma_kernel(
    const float* __restrict__ A, const float* __restrict__ W,
    const float* __restrict__ bias, float* __restrict__ C)
{
    gemm_body_v2(A, W, bias, C, dynsm);
}

__global__ __launch_bounds__(512) void gemm_kv_kernel(
    const float* __restrict__ A,
    const float* __restrict__ Wk, const float* __restrict__ bk, float* __restrict__ K,
    const float* __restrict__ Wv, const float* __restrict__ bv, float* __restrict__ V)
{
    if (blockIdx.z == 0)
        gemm_body_v2(A, Wk, bk, K, dynsm);
    else
        gemm_body_v2(A, Wv, bv, V, dynsm);
}

// ---------------------------------------------------------------------------
// 3xTF32 compensated GEMM (near-fp32) — q projection. Same pipeline skeleton.
// ---------------------------------------------------------------------------
#define G3_SMEM ((4*128*GSA + 4*32*GSB) * 4)

__global__ __launch_bounds__(512) void gemm_mma3_kernel(
    const float* __restrict__ A, const float* __restrict__ W,
    const float* __restrict__ bias, float* __restrict__ C)
{
    uint32_t* s3 = dynsm;
    uint32_t* AsH = s3;                     // [2][128*GSA]
    uint32_t* AsL = s3 + 2 * 128 * GSA;     // [2][128*GSA]
    uint32_t* BsH = s3 + 4 * 128 * GSA;     // [2][32*GSB]
    uint32_t* BsL = BsH + 2 * 32 * GSB;     // [2][32*GSB]

    const int tid = threadIdx.x, lane = tid & 31, wid = tid >> 5;
    const int wm = wid & 7, wn = wid >> 3;
    const int bm = blockIdx.x * 128, bn = blockIdx.y * 128;
    const int lq = lane >> 2, lr = lane & 3;

    float acc[8][4];
    #pragma unroll
    for (int j = 0; j < 8; j++)
        #pragma unroll
        for (int t = 0; t < 4; t++) acc[j][t] = 0.f;

    auto stageA = [&](int buf, int l, float4 v) {
        int idx = tid + l * 512;
        uint32_t* dh = &AsH[buf * 128 * GSA + (idx >> 3) * GSA + (idx & 7) * 4];
        uint32_t* dl = &AsL[buf * 128 * GSA + (idx >> 3) * GSA + (idx & 7) * 4];
        uint32_t h;
        h = f2tf32(v.x); dh[0] = h; dl[0] = f2tf32(v.x - __uint_as_float(h));
        h = f2tf32(v.y); dh[1] = h; dl[1] = f2tf32(v.y - __uint_as_float(h));
        h = f2tf32(v.z); dh[2] = h; dl[2] = f2tf32(v.z - __uint_as_float(h));
        h = f2tf32(v.w); dh[3] = h; dl[3] = f2tf32(v.w - __uint_as_float(h));
    };
    auto stageB = [&](int buf, int l, float4 v) {
        int idx = tid + l * 512;
        uint32_t* dh = &BsH[buf * 32 * GSB + (idx >> 5) * GSB + (idx & 31) * 4];
        uint32_t* dl = &BsL[buf * 32 * GSB + (idx >> 5) * GSB + (idx & 31) * 4];
        uint32_t h;
        h = f2tf32(v.x); dh[0] = h; dl[0] = f2tf32(v.x - __uint_as_float(h));
        h = f2tf32(v.y); dh[1] = h; dl[1] = f2tf32(v.y - __uint_as_float(h));
        h = f2tf32(v.z); dh[2] = h; dl[2] = f2tf32(v.z - __uint_as_float(h));
        h = f2tf32(v.w); dh[3] = h; dl[3] = f2tf32(v.w - __uint_as_float(h));
    };

    // prologue
    #pragma unroll
    for (int l = 0; l < 2; l++) {
        int idx = tid + l * 512;
        stageA(0, l, *reinterpret_cast<const float4*>(
            &A[(size_t)(bm + (idx >> 3)) * NC + (idx & 7) * 4]));
        stageB(0, l, *reinterpret_cast<const float4*>(
            &W[(size_t)(idx >> 5) * NC + bn + (idx & 31) * 4]));
    }
    __syncthreads();

    for (int c = 0; c < NCH; c++) {
        const int buf = c & 1;
        const bool more = (c + 1 < NCH);
        float4 pa[2], pb[2];
        if (more) {
            #pragma unroll
            for (int l = 0; l < 2; l++) {
                int idx = tid + l * 512;
                pa[l] = *reinterpret_cast<const float4*>(
                    &A[(size_t)(bm + (idx >> 3)) * NC + (c + 1) * 32 + (idx & 7) * 4]);
                pb[l] = *reinterpret_cast<const float4*>(
                    &W[(size_t)((c + 1) * 32 + (idx >> 5)) * NC + bn + (idx & 31) * 4]);
            }
        }
        const uint32_t* AbH = AsH + buf * 128 * GSA;
        const uint32_t* AbL = AsL + buf * 128 * GSA;
        const uint32_t* BbH = BsH + buf * 32 * GSB;
        const uint32_t* BbL = BsL + buf * 32 * GSB;
        #pragma unroll
        for (int ks = 0; ks < 4; ks++) {
            const int k0 = ks * 8;
            uint32_t afh[4], afl[4];
            const int rb = wm * 16;
            afh[0] = AbH[(rb +     lq) * GSA + k0 +     lr];
            afh[1] = AbH[(rb + 8 + lq) * GSA + k0 +     lr];
            afh[2] = AbH[(rb +     lq) * GSA + k0 + 4 + lr];
            afh[3] = AbH[(rb + 8 + lq) * GSA + k0 + 4 + lr];
            afl[0] = AbL[(rb +     lq) * GSA + k0 +     lr];
            afl[1] = AbL[(rb + 8 + lq) * GSA + k0 +     lr];
            afl[2] = AbL[(rb +     lq) * GSA + k0 + 4 + lr];
            afl[3] = AbL[(rb + 8 + lq) * GSA + k0 + 4 + lr];
            #pragma unroll
            for (int j = 0; j < 8; j++) {
                uint32_t bfh[2], bfl[2];
                const int col = wn * 64 + j * 8 + lq;
                bfh[0] = BbH[(k0 +     lr) * GSB + col];
                bfh[1] = BbH[(k0 + 4 + lr) * GSB + col];
                bfl[0] = BbL[(k0 +     lr) * GSB + col];
                bfl[1] = BbL[(k0 + 4 + lr) * GSB + col];
                mma_tf32(acc[j], afl, bfh);
                mma_tf32(acc[j], afh, bfl);
                mma_tf32(acc[j], afh, bfh);
            }
        }
        if (more) {
            #pragma unroll
            for (int l = 0; l < 2; l++) {
                stageA(buf ^ 1, l, pa[l]);
                stageB(buf ^ 1, l, pb[l]);
            }
        }
        __syncthreads();
    }

    #pragma unroll
    for (int j = 0; j < 8; j++) {
        const int col = bn + wn * 64 + j * 8 + lr * 2;
        const float b0 = bias[col], b1 = bias[col + 1];
        const int r0 = bm + wm * 16 + lq;
        *reinterpret_cast<float2*>(&C[(size_t)r0 * NC + col]) =
            make_float2(acc[j][0] + b0, acc[j][1] + b1);
        *reinterpret_cast<float2*>(&C[(size_t)(r0 + 8) * NC + col]) =
            make_float2(acc[j][2] + b0, acc[j][3] + b1);
    }
}

// ---------------------------------------------------------------------------
// Flash attention (fixed-max softmax, double-buffered K/V).
// ---------------------------------------------------------------------------
#define KS_STR 72
#define VS_STR 40
#define PS_STR 68
#define QS_STR 36
#define ATTN_SMEM ((2*32*KS_STR + 2*64*VS_STR + 8*16*PS_STR) * 4)

__global__ __launch_bounds__(256) void attn_mma_kernel()
{
    float* smf = reinterpret_cast<float*>(dynsm);
    float* KsB = smf;
    float* VsB = smf + 2 * 32 * KS_STR;
    float* Ps  = smf + 2 * 32 * KS_STR + 2 * 64 * VS_STR;

    const int tid = threadIdx.x, lane = tid & 31, wid = tid >> 5;
    const int lq = lane >> 2, lr = lane & 3;
    const int qt = blockIdx.x, h = blockIdx.y, b = blockIdx.z;
    const int q0 = qt * 128;

    const float qscale = 0.17677669529663689f * 1.4426950408889634f;
    float* Qs = Ps;
    #pragma unroll
    for (int l = 0; l < 4; l++) {
        int idx = tid + l * 256;
        int row = idx >> 3, c4 = idx & 7;
        float4 v = *reinterpret_cast<const float4*>(
            &g_q[((size_t)b * NPIX + q0 + row) * NC + h * HC + c4 * 4]);
        uint32_t* d = reinterpret_cast<uint32_t*>(&Qs[row * QS_STR + c4 * 4]);
        d[0] = f2tf32(v.x * qscale); d[1] = f2tf32(v.y * qscale);
        d[2] = f2tf32(v.z * qscale); d[3] = f2tf32(v.w * qscale);
    }
    __syncthreads();
    uint32_t qf[4][4];
    {
        const uint32_t* Q = reinterpret_cast<const uint32_t*>(Qs);
        const int rb = wid * 16;
        #pragma unroll
        for (int ks = 0; ks < 4; ks++) {
            const int k0 = ks * 8;
            qf[ks][0] = Q[(rb +     lq) * QS_STR + k0 +     lr];
            qf[ks][1] = Q[(rb + 8 + lq) * QS_STR + k0 +     lr];
            qf[ks][2] = Q[(rb +     lq) * QS_STR + k0 + 4 + lr];
            qf[ks][3] = Q[(rb + 8 + lq) * QS_STR + k0 + 4 + lr];
        }
    }
    __syncthreads();

    float o[4][4];
    #pragma unroll
    for (int j = 0; j < 4; j++)
        #pragma unroll
        for (int t = 0; t < 4; t++) o[j][t] = 0.f;
    float l0 = 0.f, l1 = 0.f;
    float* Pw = Ps + wid * 16 * PS_STR;

    auto stage = [&](int kt, int buf) {
        float* Ksm = KsB + buf * 32 * KS_STR;
        float* Vsm = VsB + buf * 64 * VS_STR;
        #pragma unroll
        for (int l = 0; l < 2; l++) {
            int idx = tid + l * 256;
            int key = idx >> 3, c4 = idx & 7;
            size_t base = ((size_t)b * NPIX + kt + key) * NC + h * HC + c4 * 4;
            float4 v = *reinterpret_cast<const float4*>(&g_k[base]);
            uint32_t* K = reinterpret_cast<uint32_t*>(Ksm);
            K[(c4 * 4 + 0) * KS_STR + key] = f2tf32(v.x);
            K[(c4 * 4 + 1) * KS_STR + key] = f2tf32(v.y);
            K[(c4 * 4 + 2) * KS_STR + key] = f2tf32(v.z);
            K[(c4 * 4 + 3) * KS_STR + key] = f2tf32(v.w);
            float4 w = *reinterpret_cast<const float4*>(&g_v[base]);
            uint32_t* V = reinterpret_cast<uint32_t*>(&Vsm[key * VS_STR + c4 * 4]);
            V[0] = f2tf32(w.x); V[1] = f2tf32(w.y);
            V[2] = f2tf32(w.z); V[3] = f2tf32(w.w);
        }
    };

    stage(0, 0);
    __syncthreads();

    for (int it = 0; it < 16; it++) {
        const int buf = it & 1;
        if (it < 15) stage((it + 1) * 64, buf ^ 1);

        const uint32_t* K = reinterpret_cast<const uint32_t*>(KsB + buf * 32 * KS_STR);
        const uint32_t* V = reinterpret_cast<const uint32_t*>(VsB + buf * 64 * VS_STR);

        float s[8][4];
        #pragma unroll
        for (int j = 0; j < 8; j++)
            #pragma unroll
            for (int t = 0; t < 4; t++) s[j][t] = 0.f;
        #pragma unroll
        for (int ks = 0; ks < 4; ks++) {
            const int k0 = ks * 8;
            #pragma unroll
            for (int j = 0; j < 8; j++) {
                uint32_t bf[2];
                const int col = j * 8 + lq;
                bf[0] = K[(k0 +     lr) * KS_STR + col];
                bf[1] = K[(k0 + 4 + lr) * KS_STR + col];
                mma_tf32(s[j], qf[ks], bf);
            }
        }

        #pragma unroll
        for (int j = 0; j < 8; j++) {
            float p00 = ex2f(s[j][0]);
            float p01 = ex2f(s[j][1]);
            float p10 = ex2f(s[j][2]);
            float p11 = ex2f(s[j][3]);
            l0 += p00 + p01;
            l1 += p10 + p11;
            const int colp = j * 8 + lr * 2;
            *reinterpret_cast<float2*>(&Pw[lq * PS_STR + colp]) = make_float2(p00, p01);
            *reinterpret_cast<float2*>(&Pw[(lq + 8) * PS_STR + colp]) = make_float2(p10, p11);
        }
        __syncwarp();

        const uint32_t* P = reinterpret_cast<const uint32_t*>(Pw);
        #pragma unroll
        for (int ks = 0; ks < 8; ks++) {
            const int k0 = ks * 8;
            uint32_t af[4];
            af[0] = P[(lq    ) * PS_STR + k0 +     lr];
            af[1] = P[(lq + 8) * PS_STR + k0 +     lr];
            af[2] = P[(lq    ) * PS_STR + k0 + 4 + lr];
            af[3] = P[(lq + 8) * PS_STR + k0 + 4 + lr];
            #pragma unroll
            for (int j = 0; j < 4; j++) {
                uint32_t bf[2];
                const int col = j * 8 + lq;
                bf[0] = V[(k0 +     lr) * VS_STR + col];
                bf[1] = V[(k0 + 4 + lr) * VS_STR + col];
                mma_tf32(o[j], af, bf);
            }
        }
        __syncthreads();
    }

    l0 += __shfl_xor_sync(0xffffffffu, l0, 1);
    l0 += __shfl_xor_sync(0xffffffffu, l0, 2);
    l1 += __shfl_xor_sync(0xffffffffu, l1, 1);
    l1 += __shfl_xor_sync(0xffffffffu, l1, 2);
    const float il0 = 1.f / l0, il1 = 1.f / l1;
    const int rg = q0 + wid * 16 + lq;
    #pragma unroll
    for (int j = 0; j < 4; j++) {
        const int col = h * HC + j * 8 + lr * 2;
        *reinterpret_cast<float2*>(&g_o[((size_t)b * NPIX + rg) * NC + col]) =
            make_float2(o[j][0] * il0, o[j][1] * il0);
        *reinterpret_cast<float2*>(&g_o[((size_t)b * NPIX + rg + 8) * NC + col]) =
            make_float2(o[j][2] * il1, o[j][3] * il1);
    }
}

// ---------------------------------------------------------------------------
// Grouped 3x3 conv (packed fma.rn.f32x2, bit-exact fp32).
// ---------------------------------------------------------------------------
#define CONV_SMEM (64 * 6 * 36 * 4)

__global__ __launch_bounds__(256) void conv_off_kernel(
    const float* __restrict__ W, const float* __restrict__ bias)
{
    float* qs = reinterpret_cast<float*>(dynsm);   // [64 ic][6 r][36 x]
    const int bid = blockIdx.x;
    const int g  = bid % GROUPS;
    const int yt = (bid / GROUPS) & 7;
    const int b  = bid / (GROUPS * 8);
    const int y0 = yt * 4;
    const int tid = threadIdx.x;

    for (int i = tid; i < 64 * 6 * 34; i += 256) {
        int c  = i & 63;
        int xx = (i >> 6) % 34;
        int r  = i / (64 * 34);
        int yy = y0 + r - 1;
        float v = 0.f;
        if (xx >= 1 && xx <= 32 && yy >= 0 && yy < HH)
            v = g_q[((size_t)(b*HH + yy)*WW + (xx-1)) * NC + g*GC + c];
        qs[(c * 6 + r) * 36 + xx] = v;
    }
    __syncthreads();

    const int ty = tid >> 6;
    const int x0 = ((tid >> 4) & 3) * 8;
    const int oc = (tid & 15) * 4;
    const int y  = y0 + ty;

    uint64_t acc01[8], acc23[8];
    {
        float4 bv = *reinterpret_cast<const float4*>(&bias[g*GC + oc]);
        uint64_t b01 = packf2(bv.x, bv.y), b23 = packf2(bv.z, bv.w);
        #pragma unroll
        for (int xi = 0; xi < 8; xi++) { acc01[xi] = b01; acc23[xi] = b23; }
    }

    #pragma unroll
    for (int dy = 0; dy < 3; dy++) {
        const int r = ty + dy;
        #pragma unroll 2
        for (int ic = 0; ic < GC; ic++) {
            const float* qrow = &qs[(ic * 6 + r) * 36 + x0];
            uint64_t qp[10];
            #pragma unroll
            for (int j = 0; j < 10; j++) {
                float qv = qrow[j];
                qp[j] = packf2(qv, qv);
            }
            const uint64_t* wp0 = reinterpret_cast<const uint64_t*>(
                &W[(size_t)((dy*3 + 0) * GC + ic) * NC + g*GC + oc]);
            const uint64_t* wp1 = reinterpret_cast<const uint64_t*>(
                &W[(size_t)((dy*3 + 1) * GC + ic) * NC + g*GC + oc]);
            const uint64_t* wp2 = reinterpret_cast<const uint64_t*>(
                &W[(size_t)((dy*3 + 2) * GC + ic) * NC + g*GC + oc]);
            const uint64_t w0a = wp0[0], w0b = wp0[1];
            const uint64_t w1a = wp1[0], w1b = wp1[1];
            const uint64_t w2a = wp2[0], w2b = wp2[1];
            #pragma unroll
            for (int xi = 0; xi < 8; xi++) {
                FMA2(acc01[xi], w0a, qp[xi]);
                FMA2(acc23[xi], w0b, qp[xi]);
                FMA2(acc01[xi], w1a, qp[xi + 1]);
                FMA2(acc23[xi], w1b, qp[xi + 1]);
                FMA2(acc01[xi], w2a, qp[xi + 2]);
                FMA2(acc23[xi], w2b, qp[xi + 2]);
            }
        }
    }

    #pragma unroll
    for (int xi = 0; xi < 8; xi++) {
        float2 a = unpackf2(acc01[xi]);
        float2 c = unpackf2(acc23[xi]);
        float4 o = make_float4(a.x, a.y, c.x, c.y);
        *reinterpret_cast<float4*>(
            &g_t[((size_t)(b*HH + y)*WW + x0 + xi) * NC + g*GC + oc]) = o;
    }
}

// ---------------------------------------------------------------------------
// Fused: LayerNorm + erf-GELU + offset proj + tanh*range + ref grid + sample.
// ---------------------------------------------------------------------------
__global__ __launch_bounds__(384) void ln_sample_kernel(
    const float* __restrict__ ln_g, const float* __restrict__ ln_b,
    const float* __restrict__ wp, const float* __restrict__ x)
{
    const int p   = blockIdx.x;
    const int tid = threadIdx.x;
    const int wid  = tid >> 5;
    const int lane = tid & 31;

    float v = g_t[(size_t)p * NC + tid];

    __shared__ float red[2][12];
    __shared__ float sv[NC];
    __shared__ float spos[12];

    float s = v, sq = v * v;
    #pragma unroll
    for (int o = 16; o > 0; o >>= 1) {
        s  += __shfl_xor_sync(0xffffffffu, s,  o);
        sq += __shfl_xor_sync(0xffffffffu, sq, o);
    }
    if (lane == 0) { red[0][wid] = s; red[1][wid] = sq; }
    __syncthreads();
    if (tid < 32) {
        float a = (tid < 12) ? red[0][tid] : 0.f;
        float c = (tid < 12) ? red[1][tid] : 0.f;
        #pragma unroll
        for (int o = 8; o > 0; o >>= 1) {
            a += __shfl_xor_sync(0xffffffffu, a, o);
            c += __shfl_xor_sync(0xffffffffu, c, o);
        }
        if (tid == 0) { red[0][0] = a; red[1][0] = c; }
    }
    __syncthreads();
    const float mu  = red[0][0] * (1.f / NC);
    const float var = red[1][0] * (1.f / NC) - mu * mu;
    float nv = (v - mu) * rsqrtf(var + 1e-3f) * ln_g[tid] + ln_b[tid];
    nv = 0.5f * nv * (1.f + erff(nv * 0.70710678118654752f));

    sv[tid] = nv;
    __syncthreads();

    const int grp = wid >> 1, comp = wid & 1;
    float part = sv[grp*GC + lane]      * wp[lane * 2 + comp]
               + sv[grp*GC + 32 + lane] * wp[(32 + lane) * 2 + comp];
    #pragma unroll
    for (int o = 16; o > 0; o >>= 1)
        part += __shfl_xor_sync(0xffffffffu, part, o);

    const int pix = p & 1023;
    if (lane == 0) {
        const int yy = pix >> 5, xx = pix & 31;
        float refv = (comp == 0) ? (float)xx : (float)yy;
        spos[grp*2 + comp] = tanhf(part) * 16.f + refv;
    }
    __syncthreads();

    const int b = p >> 10;
    const int g = tid >> 6, c = tid & 63;
    const float p0 = spos[g*2 + 0];
    const float p1 = spos[g*2 + 1];
    const float xqf = p1 + 1.f;
    const float yqf = p0 + 1.f;
    const float x0f = fminf(fmaxf(floorf(xqf), 0.f), 32.f);
    const float y0f = fminf(fmaxf(floorf(yqf), 0.f), 32.f);
    const float ax = fminf(fmaxf(xqf - x0f, 0.f), 1.f);
    const float ay = fminf(fmaxf(yqf - y0f, 0.f), 1.f);
    const int x0 = (int)x0f, y0 = (int)y0f;

    const size_t choff = (size_t)g * GC + c;
    auto fetch = [&](int yy2, int xx2) -> float {
        if (yy2 < 1 || yy2 > 32 || xx2 < 1 || xx2 > 32) return 0.f;
        return x[((size_t)(b*HH + (yy2-1)) * WW + (xx2-1)) * NC + choff];
    };
    float tl = fetch(y0,     x0);
    float tr = fetch(y0,     x0 + 1);
    float bl = fetch(y0 + 1, x0);
    float br = fetch(y0 + 1, x0 + 1);
    float top = tl + ax * (tr - tl);
    float bot = bl + ax * (br - bl);
    g_xs[((size_t)b * NPIX + pix) * NC + choff] = top + ay * (bot - top);
}

// ---------------------------------------------------------------------------
// Launch
// ---------------------------------------------------------------------------
extern "C" void kernel_launch(void* const* d_in, const int* in_sizes, int n_in,
                              void* d_out, int out_size)
{
    const float* x      = (const float*)d_in[0];
    const float* w_q    = (const float*)d_in[1];
    const float* b_q    = (const float*)d_in[2];
    const float* w_off0 = (const float*)d_in[3];
    const float* b_off0 = (const float*)d_in[4];
    const float* ln_g   = (const float*)d_in[5];
    const float* ln_b   = (const float*)d_in[6];
    const float* w_offp = (const float*)d_in[7];
    const float* w_k    = (const float*)d_in[8];
    const float* b_k    = (const float*)d_in[9];
    const float* w_v    = (const float*)d_in[10];
    const float* b_v    = (const float*)d_in[11];
    const float* w_o    = (const float*)d_in[12];
    const float* b_o    = (const float*)d_in[13];
    float* out = (float*)d_out;

    float *pq, *pxs, *pk, *pv, *po;
    cudaGetSymbolAddress((void**)&pq,  g_q);
    cudaGetSymbolAddress((void**)&pxs, g_xs);
    cudaGetSymbolAddress((void**)&pk,  g_k);
    cudaGetSymbolAddress((void**)&pv,  g_v);
    cudaGetSymbolAddress((void**)&po,  g_o);

    cudaFuncSetAttribute(attn_mma_kernel,
                         cudaFuncAttributeMaxDynamicSharedMemorySize, ATTN_SMEM);
    cudaFuncSetAttribute(gemm_mma3_kernel,
                         cudaFuncAttributeMaxDynamicSharedMemorySize, G3_SMEM);
    cudaFuncSetAttribute(gemm_mma_kernel,
                         cudaFuncAttributeMaxDynamicSharedMemorySize, GEMM_SMEM);
    cudaFuncSetAttribute(gemm_kv_kernel,
                         cudaFuncAttributeMaxDynamicSharedMemorySize, GEMM_SMEM);
    cudaFuncSetAttribute(conv_off_kernel,
                         cudaFuncAttributeMaxDynamicSharedMemorySize, CONV_SMEM);

    dim3 ggrid(MTOT / 128, NC / 128);
    dim3 kvgrid(MTOT / 128, NC / 128, 2);
    dim3 agrid(NPIX / 128, HEADS, BB);

    // 1. q = x @ w_q + b_q   (3xTF32 compensated, pipelined)
    gemm_mma3_kernel<<<ggrid, 512, G3_SMEM>>>(x, w_q, b_q, pq);
    // 2. grouped 3x3 conv on q -> g_t
    conv_off_kernel<<<BB * 8 * GROUPS, 256, CONV_SMEM>>>(w_off0, b_off0);
    // 3. LN + GELU + offset proj + tanh + ref + bilinear sample -> g_xs
    ln_sample_kernel<<<MTOT, NC>>>(ln_g, ln_b, w_offp, x);
    // 4. fused k+v projections (pipelined tf32 mma)
    gemm_kv_kernel<<<kvgrid, 512, GEMM_SMEM>>>(pxs, w_k, b_k, pk, w_v, b_v, pv);
    // 5. attention (tf32 mma flash, fixed-max softmax) -> g_o
    attn_mma_kernel<<<agrid, 256, ATTN_SMEM>>>();
    // 6. y = o @ w_o + b_o -> d_out
    gemm_mma_kernel<<<ggrid, 512, GEMM_SMEM>>>(po, w_o, b_o, out);
}

// round 9
// speedup vs baseline: 1.0777x; 1.0777x over previous
#include <cuda_runtime.h>
#include <math.h>
#include <stdint.h>

// ---------------------------------------------------------------------------
// Problem constants
// ---------------------------------------------------------------------------
#define BB     8
#define HH     32
#define WW     32
#define NC     384
#define GROUPS 6
#define HEADS  12
#define HC     32
#define GC     64
#define NPIX   (HH*WW)          // 1024
#define MTOT   (BB*NPIX)        // 8192
#define NCH    12               // K chunks of 32

// ---------------------------------------------------------------------------
// Scratch (static device globals — no allocation allowed)
// ---------------------------------------------------------------------------
__device__ float g_q  [MTOT*NC];
__device__ float g_t  [MTOT*NC];
__device__ float g_xs [MTOT*NC];
__device__ float g_k  [MTOT*NC];
__device__ float g_v  [MTOT*NC];
__device__ float g_o  [MTOT*NC];

// ---------------------------------------------------------------------------
// mma.sync / packed-f32x2 / cp.async helpers (base sm_103 ISA)
// ---------------------------------------------------------------------------
__device__ __forceinline__ uint32_t f2tf32(float x) {
    uint32_t r;
    asm("cvt.rna.tf32.f32 %0, %1;" : "=r"(r) : "f"(x));
    return r;
}
__device__ __forceinline__ float ex2f(float x) {
    float r;
    asm("ex2.approx.f32 %0, %1;" : "=f"(r) : "f"(x));
    return r;
}
__device__ __forceinline__ void mma_tf32(float* c, const uint32_t* a, const uint32_t* b) {
    asm volatile(
        "mma.sync.aligned.m16n8k8.row.col.f32.tf32.tf32.f32 "
        "{%0,%1,%2,%3}, {%4,%5,%6,%7}, {%8,%9}, {%0,%1,%2,%3};"
        : "+f"(c[0]), "+f"(c[1]), "+f"(c[2]), "+f"(c[3])
        : "r"(a[0]), "r"(a[1]), "r"(a[2]), "r"(a[3]), "r"(b[0]), "r"(b[1]));
}
#define FMA2(d, a, b) \
    asm("fma.rn.f32x2 %0, %1, %2, %0;" : "+l"(d) : "l"(a), "l"(b))
__device__ __forceinline__ uint64_t packf2(float lo, float hi) {
    uint64_t r;
    asm("mov.b64 %0, {%1, %2};" : "=l"(r) : "f"(lo), "f"(hi));
    return r;
}
__device__ __forceinline__ float2 unpackf2(uint64_t v) {
    float2 r;
    asm("mov.b64 {%0, %1}, %2;" : "=f"(r.x), "=f"(r.y) : "l"(v));
    return r;
}
__device__ __forceinline__ void cp16(uint32_t saddr, const void* gptr) {
    asm volatile("cp.async.ca.shared.global [%0], [%1], 16;"
                 :: "r"(saddr), "l"(gptr));
}
#define CP_COMMIT() asm volatile("cp.async.commit_group;" ::: "memory")
#define CP_WAIT0()  asm volatile("cp.async.wait_group 0;"  ::: "memory")

// single dynamic-smem symbol for the whole TU
extern __shared__ uint32_t dynsm[];

// ---------------------------------------------------------------------------
// Pipelined tf32 mma GEMM: 256 thr, 8 warps (4m x 2n), warp tile 32x64 (R6
// shape), cp.async double-buffered RAW fp32 tiles, cvt.rna at fragment load
// (bit-identical to cvt-at-store). ONE __syncthreads per K-chunk.
// ---------------------------------------------------------------------------
#define GSA 36    // A row stride (floats); 144 B, 16B-multiple
#define GSB 136   // B row stride (floats); 544 B, 16B-multiple
#define GEMM_SMEM ((2*128*GSA + 2*32*GSB) * 4)

__device__ __forceinline__ void gemm_body_v3(
    const float* __restrict__ A, const float* __restrict__ W,
    const float* __restrict__ bias, float* __restrict__ C)
{
    float* As = reinterpret_cast<float*>(dynsm);        // [2][128*GSA]
    float* Bs = As + 2 * 128 * GSA;                     // [2][32*GSB]
    const uint32_t sA = (uint32_t)__cvta_generic_to_shared(As);
    const uint32_t sB = (uint32_t)__cvta_generic_to_shared(Bs);

    const int tid = threadIdx.x, lane = tid & 31, wid = tid >> 5;
    const int wm = wid & 3, wn = wid >> 2;
    const int bm = blockIdx.x * 128, bn = blockIdx.y * 128;
    const int lq = lane >> 2, lr = lane & 3;

    float acc[2][8][4];
    #pragma unroll
    for (int i = 0; i < 2; i++)
        #pragma unroll
        for (int j = 0; j < 8; j++)
            #pragma unroll
            for (int t = 0; t < 4; t++) acc[i][j][t] = 0.f;

    // async-stage chunk c into buffer buf (4 A + 4 B 16B copies per thread)
    auto stage = [&](int c, int buf) {
        #pragma unroll
        for (int l = 0; l < 4; l++) {
            int idx = tid + l * 256;                 // 0..1023
            int ra = idx >> 3, ca = idx & 7;         // A: 128 x 8(c4)
            cp16(sA + (buf * 128 * GSA + ra * GSA + ca * 4) * 4,
                 &A[(size_t)(bm + ra) * NC + c * 32 + ca * 4]);
            int rb = idx >> 5, cb = idx & 31;        // B: 32 x 32(c4)
            cp16(sB + (buf * 32 * GSB + rb * GSB + cb * 4) * 4,
                 &W[(size_t)(c * 32 + rb) * NC + bn + cb * 4]);
        }
        CP_COMMIT();
    };

    stage(0, 0);
    CP_WAIT0();
    __syncthreads();

    for (int c = 0; c < NCH; c++) {
        const int buf = c & 1;
        const bool more = (c + 1 < NCH);
        if (more) stage(c + 1, buf ^ 1);     // overlaps with compute below

        const float* Ab = As + buf * 128 * GSA;
        const float* Bb = Bs + buf * 32 * GSB;
        #pragma unroll
        for (int ks = 0; ks < 4; ks++) {
            const int k0 = ks * 8;
            uint32_t af[2][4];
            #pragma unroll
            for (int i = 0; i < 2; i++) {
                const int rb = wm * 32 + i * 16;
                af[i][0] = f2tf32(Ab[(rb +     lq) * GSA + k0 +     lr]);
                af[i][1] = f2tf32(Ab[(rb + 8 + lq) * GSA + k0 +     lr]);
                af[i][2] = f2tf32(Ab[(rb +     lq) * GSA + k0 + 4 + lr]);
                af[i][3] = f2tf32(Ab[(rb + 8 + lq) * GSA + k0 + 4 + lr]);
            }
            #pragma unroll
            for (int j = 0; j < 8; j++) {
                uint32_t bf[2];
                const int col = wn * 64 + j * 8 + lq;
                bf[0] = f2tf32(Bb[(k0 +     lr) * GSB + col]);
                bf[1] = f2tf32(Bb[(k0 + 4 + lr) * GSB + col]);
                mma_tf32(acc[0][j], af[0], bf);
                mma_tf32(acc[1][j], af[1], bf);
            }
        }
        if (more) CP_WAIT0();
        __syncthreads();
    }

    #pragma unroll
    for (int j = 0; j < 8; j++) {
        const int col = bn + wn * 64 + j * 8 + lr * 2;
        const float b0 = bias[col], b1 = bias[col + 1];
        #pragma unroll
        for (int i = 0; i < 2; i++) {
            const int r0 = bm + wm * 32 + i * 16 + lq;
            *reinterpret_cast<float2*>(&C[(size_t)r0 * NC + col]) =
                make_float2(acc[i][j][0] + b0, acc[i][j][1] + b1);
            *reinterpret_cast<float2*>(&C[(size_t)(r0 + 8) * NC + col]) =
                make_float2(acc[i][j][2] + b0, acc[i][j][3] + b1);
        }
    }
}

__global__ __launch_bounds__(256) void gemm_mma_kernel(
    const float* __restrict__ A, const float* __restrict__ W,
    const float* __restrict__ bias, float* __restrict__ C)
{
    gemm_body_v3(A, W, bias, C);
}

__global__ __launch_bounds__(256) void gemm_kv_kernel(
    const float* __restrict__ A,
    const float* __restrict__ Wk, const float* __restrict__ bk, float* __restrict__ K,
    const float* __restrict__ Wv, const float* __restrict__ bv, float* __restrict__ V)
{
    if (blockIdx.z == 0)
        gemm_body_v3(A, Wk, bk, K);
    else
        gemm_body_v3(A, Wv, bv, V);
}

// ---------------------------------------------------------------------------
// 3xTF32 compensated GEMM (near-fp32) — q projection only. R6-proven version
// (256 thr, 2 m-tiles, single-buffered).
// ---------------------------------------------------------------------------
#define G3_SMEM ((128*GSA*2 + 32*GSB*2) * 4)

__global__ __launch_bounds__(256) void gemm_mma3_kernel(
    const float* __restrict__ A, const float* __restrict__ W,
    const float* __restrict__ bias, float* __restrict__ C)
{
    uint32_t* s3 = dynsm;
    uint32_t* AsH = s3;
    uint32_t* AsL = s3 + 128 * GSA;
    uint32_t* BsH = s3 + 2 * 128 * GSA;
    uint32_t* BsL = BsH + 32 * GSB;

    const int tid = threadIdx.x, lane = tid & 31, wid = tid >> 5;
    const int wm = wid & 3, wn = wid >> 2;
    const int bm = blockIdx.x * 128, bn = blockIdx.y * 128;
    const int lq = lane >> 2, lr = lane & 3;

    float acc[2][8][4];
    #pragma unroll
    for (int i = 0; i < 2; i++)
        #pragma unroll
        for (int j = 0; j < 8; j++)
            #pragma unroll
            for (int t = 0; t < 4; t++) acc[i][j][t] = 0.f;

    for (int c = 0; c < NCH; c++) {
        #pragma unroll
        for (int l = 0; l < 4; l++) {
            int idx = tid + l * 256;
            int row = idx >> 3, c4 = idx & 7;
            float4 v = *reinterpret_cast<const float4*>(
                &A[(size_t)(bm + row) * NC + c * 32 + c4 * 4]);
            uint32_t* dh = &AsH[row * GSA + c4 * 4];
            uint32_t* dl = &AsL[row * GSA + c4 * 4];
            uint32_t h;
            h = f2tf32(v.x); dh[0] = h; dl[0] = f2tf32(v.x - __uint_as_float(h));
            h = f2tf32(v.y); dh[1] = h; dl[1] = f2tf32(v.y - __uint_as_float(h));
            h = f2tf32(v.z); dh[2] = h; dl[2] = f2tf32(v.z - __uint_as_float(h));
            h = f2tf32(v.w); dh[3] = h; dl[3] = f2tf32(v.w - __uint_as_float(h));
        }
        #pragma unroll
        for (int l = 0; l < 4; l++) {
            int idx = tid + l * 256;
            int row = idx >> 5, c4 = idx & 31;
            float4 v = *reinterpret_cast<const float4*>(
                &W[(size_t)(c * 32 + row) * NC + bn + c4 * 4]);
            uint32_t* dh = &BsH[row * GSB + c4 * 4];
            uint32_t* dl = &BsL[row * GSB + c4 * 4];
            uint32_t h;
            h = f2tf32(v.x); dh[0] = h; dl[0] = f2tf32(v.x - __uint_as_float(h));
            h = f2tf32(v.y); dh[1] = h; dl[1] = f2tf32(v.y - __uint_as_float(h));
            h = f2tf32(v.z); dh[2] = h; dl[2] = f2tf32(v.z - __uint_as_float(h));
            h = f2tf32(v.w); dh[3] = h; dl[3] = f2tf32(v.w - __uint_as_float(h));
        }
        __syncthreads();
        #pragma unroll
        for (int ks = 0; ks < 4; ks++) {
            const int k0 = ks * 8;
            uint32_t afh[2][4], afl[2][4];
            #pragma unroll
            for (int i = 0; i < 2; i++) {
                const int rb = wm * 32 + i * 16;
                afh[i][0] = AsH[(rb +     lq) * GSA + k0 +     lr];
                afh[i][1] = AsH[(rb + 8 + lq) * GSA + k0 +     lr];
                afh[i][2] = AsH[(rb +     lq) * GSA + k0 + 4 + lr];
                afh[i][3] = AsH[(rb + 8 + lq) * GSA + k0 + 4 + lr];
                afl[i][0] = AsL[(rb +     lq) * GSA + k0 +     lr];
                afl[i][1] = AsL[(rb + 8 + lq) * GSA + k0 +     lr];
                afl[i][2] = AsL[(rb +     lq) * GSA + k0 + 4 + lr];
                afl[i][3] = AsL[(rb + 8 + lq) * GSA + k0 + 4 + lr];
            }
            #pragma unroll
            for (int j = 0; j < 8; j++) {
                uint32_t bfh[2], bfl[2];
                const int col = wn * 64 + j * 8 + lq;
                bfh[0] = BsH[(k0 +     lr) * GSB + col];
                bfh[1] = BsH[(k0 + 4 + lr) * GSB + col];
                bfl[0] = BsL[(k0 +     lr) * GSB + col];
                bfl[1] = BsL[(k0 + 4 + lr) * GSB + col];
                #pragma unroll
                for (int i = 0; i < 2; i++) {
                    mma_tf32(acc[i][j], afl[i], bfh);
                    mma_tf32(acc[i][j], afh[i], bfl);
                    mma_tf32(acc[i][j], afh[i], bfh);
                }
            }
        }
        __syncthreads();
    }
    #pragma unroll
    for (int j = 0; j < 8; j++) {
        const int col = bn + wn * 64 + j * 8 + lr * 2;
        const float b0 = bias[col], b1 = bias[col + 1];
        #pragma unroll
        for (int i = 0; i < 2; i++) {
            const int r0 = bm + wm * 32 + i * 16 + lq;
            *reinterpret_cast<float2*>(&C[(size_t)r0 * NC + col]) =
                make_float2(acc[i][j][0] + b0, acc[i][j][1] + b1);
            *reinterpret_cast<float2*>(&C[(size_t)(r0 + 8) * NC + col]) =
                make_float2(acc[i][j][2] + b0, acc[i][j][3] + b1);
        }
    }
}

// ---------------------------------------------------------------------------
// Flash attention (fixed-max softmax, double-buffered K/V) — R6-proven.
// ---------------------------------------------------------------------------
#define KS_STR 72
#define VS_STR 40
#define PS_STR 68
#define QS_STR 36
#define ATTN_SMEM ((2*32*KS_STR + 2*64*VS_STR + 8*16*PS_STR) * 4)

__global__ __launch_bounds__(256) void attn_mma_kernel()
{
    float* smf = reinterpret_cast<float*>(dynsm);
    float* KsB = smf;
    float* VsB = smf + 2 * 32 * KS_STR;
    float* Ps  = smf + 2 * 32 * KS_STR + 2 * 64 * VS_STR;

    const int tid = threadIdx.x, lane = tid & 31, wid = tid >> 5;
    const int lq = lane >> 2, lr = lane & 3;
    const int qt = blockIdx.x, h = blockIdx.y, b = blockIdx.z;
    const int q0 = qt * 128;

    const float qscale = 0.17677669529663689f * 1.4426950408889634f;
    float* Qs = Ps;
    #pragma unroll
    for (int l = 0; l < 4; l++) {
        int idx = tid + l * 256;
        int row = idx >> 3, c4 = idx & 7;
        float4 v = *reinterpret_cast<const float4*>(
            &g_q[((size_t)b * NPIX + q0 + row) * NC + h * HC + c4 * 4]);
        uint32_t* d = reinterpret_cast<uint32_t*>(&Qs[row * QS_STR + c4 * 4]);
        d[0] = f2tf32(v.x * qscale); d[1] = f2tf32(v.y * qscale);
        d[2] = f2tf32(v.z * qscale); d[3] = f2tf32(v.w * qscale);
    }
    __syncthreads();
    uint32_t qf[4][4];
    {
        const uint32_t* Q = reinterpret_cast<const uint32_t*>(Qs);
        const int rb = wid * 16;
        #pragma unroll
        for (int ks = 0; ks < 4; ks++) {
            const int k0 = ks * 8;
            qf[ks][0] = Q[(rb +     lq) * QS_STR + k0 +     lr];
            qf[ks][1] = Q[(rb + 8 + lq) * QS_STR + k0 +     lr];
            qf[ks][2] = Q[(rb +     lq) * QS_STR + k0 + 4 + lr];
            qf[ks][3] = Q[(rb + 8 + lq) * QS_STR + k0 + 4 + lr];
        }
    }
    __syncthreads();

    float o[4][4];
    #pragma unroll
    for (int j = 0; j < 4; j++)
        #pragma unroll
        for (int t = 0; t < 4; t++) o[j][t] = 0.f;
    float l0 = 0.f, l1 = 0.f;
    float* Pw = Ps + wid * 16 * PS_STR;

    auto stage = [&](int kt, int buf) {
        float* Ksm = KsB + buf * 32 * KS_STR;
        float* Vsm = VsB + buf * 64 * VS_STR;
        #pragma unroll
        for (int l = 0; l < 2; l++) {
            int idx = tid + l * 256;
            int key = idx >> 3, c4 = idx & 7;
            size_t base = ((size_t)b * NPIX + kt + key) * NC + h * HC + c4 * 4;
            float4 v = *reinterpret_cast<const float4*>(&g_k[base]);
            uint32_t* K = reinterpret_cast<uint32_t*>(Ksm);
            K[(c4 * 4 + 0) * KS_STR + key] = f2tf32(v.x);
            K[(c4 * 4 + 1) * KS_STR + key] = f2tf32(v.y);
            K[(c4 * 4 + 2) * KS_STR + key] = f2tf32(v.z);
            K[(c4 * 4 + 3) * KS_STR + key] = f2tf32(v.w);
            float4 w = *reinterpret_cast<const float4*>(&g_v[base]);
            uint32_t* V = reinterpret_cast<uint32_t*>(&Vsm[key * VS_STR + c4 * 4]);
            V[0] = f2tf32(w.x); V[1] = f2tf32(w.y);
            V[2] = f2tf32(w.z); V[3] = f2tf32(w.w);
        }
    };

    stage(0, 0);
    __syncthreads();

    for (int it = 0; it < 16; it++) {
        const int buf = it & 1;
        if (it < 15) stage((it + 1) * 64, buf ^ 1);

        const uint32_t* K = reinterpret_cast<const uint32_t*>(KsB + buf * 32 * KS_STR);
        const uint32_t* V = reinterpret_cast<const uint32_t*>(VsB + buf * 64 * VS_STR);

        float s[8][4];
        #pragma unroll
        for (int j = 0; j < 8; j++)
            #pragma unroll
            for (int t = 0; t < 4; t++) s[j][t] = 0.f;
        #pragma unroll
        for (int ks = 0; ks < 4; ks++) {
            const int k0 = ks * 8;
            #pragma unroll
            for (int j = 0; j < 8; j++) {
                uint32_t bf[2];
                const int col = j * 8 + lq;
                bf[0] = K[(k0 +     lr) * KS_STR + col];
                bf[1] = K[(k0 + 4 + lr) * KS_STR + col];
                mma_tf32(s[j], qf[ks], bf);
            }
        }

        #pragma unroll
        for (int j = 0; j < 8; j++) {
            float p00 = ex2f(s[j][0]);
            float p01 = ex2f(s[j][1]);
            float p10 = ex2f(s[j][2]);
            float p11 = ex2f(s[j][3]);
            l0 += p00 + p01;
            l1 += p10 + p11;
            const int colp = j * 8 + lr * 2;
            *reinterpret_cast<float2*>(&Pw[lq * PS_STR + colp]) = make_float2(p00, p01);
            *reinterpret_cast<float2*>(&Pw[(lq + 8) * PS_STR + colp]) = make_float2(p10, p11);
        }
        __syncwarp();

        const uint32_t* P = reinterpret_cast<const uint32_t*>(Pw);
        #pragma unroll
        for (int ks = 0; ks < 8; ks++) {
            const int k0 = ks * 8;
            uint32_t af[4];
            af[0] = P[(lq    ) * PS_STR + k0 +     lr];
            af[1] = P[(lq + 8) * PS_STR + k0 +     lr];
            af[2] = P[(lq    ) * PS_STR + k0 + 4 + lr];
            af[3] = P[(lq + 8) * PS_STR + k0 + 4 + lr];
            #pragma unroll
            for (int j = 0; j < 4; j++) {
                uint32_t bf[2];
                const int col = j * 8 + lq;
                bf[0] = V[(k0 +     lr) * VS_STR + col];
                bf[1] = V[(k0 + 4 + lr) * VS_STR + col];
                mma_tf32(o[j], af, bf);
            }
        }
        __syncthreads();
    }

    l0 += __shfl_xor_sync(0xffffffffu, l0, 1);
    l0 += __shfl_xor_sync(0xffffffffu, l0, 2);
    l1 += __shfl_xor_sync(0xffffffffu, l1, 1);
    l1 += __shfl_xor_sync(0xffffffffu, l1, 2);
    const float il0 = 1.f / l0, il1 = 1.f / l1;
    const int rg = q0 + wid * 16 + lq;
    #pragma unroll
    for (int j = 0; j < 4; j++) {
        const int col = h * HC + j * 8 + lr * 2;
        *reinterpret_cast<float2*>(&g_o[((size_t)b * NPIX + rg) * NC + col]) =
            make_float2(o[j][0] * il0, o[j][1] * il0);
        *reinterpret_cast<float2*>(&g_o[((size_t)b * NPIX + rg + 8) * NC + col]) =
            make_float2(o[j][2] * il1, o[j][3] * il1);
    }
}

// ---------------------------------------------------------------------------
// Grouped 3x3 conv (packed fma.rn.f32x2, bit-exact fp32) — unchanged.
// ---------------------------------------------------------------------------
#define CONV_SMEM (64 * 6 * 36 * 4)

__global__ __launch_bounds__(256) void conv_off_kernel(
    const float* __restrict__ W, const float* __restrict__ bias)
{
    float* qs = reinterpret_cast<float*>(dynsm);   // [64 ic][6 r][36 x]
    const int bid = blockIdx.x;
    const int g  = bid % GROUPS;
    const int yt = (bid / GROUPS) & 7;
    const int b  = bid / (GROUPS * 8);
    const int y0 = yt * 4;
    const int tid = threadIdx.x;

    for (int i = tid; i < 64 * 6 * 34; i += 256) {
        int c  = i & 63;
        int xx = (i >> 6) % 34;
        int r  = i / (64 * 34);
        int yy = y0 + r - 1;
        float v = 0.f;
        if (xx >= 1 && xx <= 32 && yy >= 0 && yy < HH)
            v = g_q[((size_t)(b*HH + yy)*WW + (xx-1)) * NC + g*GC + c];
        qs[(c * 6 + r) * 36 + xx] = v;
    }
    __syncthreads();

    const int ty = tid >> 6;
    const int x0 = ((tid >> 4) & 3) * 8;
    const int oc = (tid & 15) * 4;
    const int y  = y0 + ty;

    uint64_t acc01[8], acc23[8];
    {
        float4 bv = *reinterpret_cast<const float4*>(&bias[g*GC + oc]);
        uint64_t b01 = packf2(bv.x, bv.y), b23 = packf2(bv.z, bv.w);
        #pragma unroll
        for (int xi = 0; xi < 8; xi++) { acc01[xi] = b01; acc23[xi] = b23; }
    }

    #pragma unroll
    for (int dy = 0; dy < 3; dy++) {
        const int r = ty + dy;
        #pragma unroll 2
        for (int ic = 0; ic < GC; ic++) {
            const float* qrow = &qs[(ic * 6 + r) * 36 + x0];
            uint64_t qp[10];
            #pragma unroll
            for (int j = 0; j < 10; j++) {
                float qv = qrow[j];
                qp[j] = packf2(qv, qv);
            }
            const uint64_t* wp0 = reinterpret_cast<const uint64_t*>(
                &W[(size_t)((dy*3 + 0) * GC + ic) * NC + g*GC + oc]);
            const uint64_t* wp1 = reinterpret_cast<const uint64_t*>(
                &W[(size_t)((dy*3 + 1) * GC + ic) * NC + g*GC + oc]);
            const uint64_t* wp2 = reinterpret_cast<const uint64_t*>(
                &W[(size_t)((dy*3 + 2) * GC + ic) * NC + g*GC + oc]);
            const uint64_t w0a = wp0[0], w0b = wp0[1];
            const uint64_t w1a = wp1[0], w1b = wp1[1];
            const uint64_t w2a = wp2[0], w2b = wp2[1];
            #pragma unroll
            for (int xi = 0; xi < 8; xi++) {
                FMA2(acc01[xi], w0a, qp[xi]);
                FMA2(acc23[xi], w0b, qp[xi]);
                FMA2(acc01[xi], w1a, qp[xi + 1]);
                FMA2(acc23[xi], w1b, qp[xi + 1]);
                FMA2(acc01[xi], w2a, qp[xi + 2]);
                FMA2(acc23[xi], w2b, qp[xi + 2]);
            }
        }
    }

    #pragma unroll
    for (int xi = 0; xi < 8; xi++) {
        float2 a = unpackf2(acc01[xi]);
        float2 c = unpackf2(acc23[xi]);
        float4 o = make_float4(a.x, a.y, c.x, c.y);
        *reinterpret_cast<float4*>(
            &g_t[((size_t)(b*HH + y)*WW + x0 + xi) * NC + g*GC + oc]) = o;
    }
}

// ---------------------------------------------------------------------------
// Fused: LayerNorm + erf-GELU + offset proj + tanh*range + ref grid + sample.
// ---------------------------------------------------------------------------
__global__ __launch_bounds__(384) void ln_sample_kernel(
    const float* __restrict__ ln_g, const float* __restrict__ ln_b,
    const float* __restrict__ wp, const float* __restrict__ x)
{
    const int p   = blockIdx.x;
    const int tid = threadIdx.x;
    const int wid  = tid >> 5;
    const int lane = tid & 31;

    float v = g_t[(size_t)p * NC + tid];

    __shared__ float red[2][12];
    __shared__ float sv[NC];
    __shared__ float spos[12];

    float s = v, sq = v * v;
    #pragma unroll
    for (int o = 16; o > 0; o >>= 1) {
        s  += __shfl_xor_sync(0xffffffffu, s,  o);
        sq += __shfl_xor_sync(0xffffffffu, sq, o);
    }
    if (lane == 0) { red[0][wid] = s; red[1][wid] = sq; }
    __syncthreads();
    if (tid < 32) {
        float a = (tid < 12) ? red[0][tid] : 0.f;
        float c = (tid < 12) ? red[1][tid] : 0.f;
        #pragma unroll
        for (int o = 8; o > 0; o >>= 1) {
            a += __shfl_xor_sync(0xffffffffu, a, o);
            c += __shfl_xor_sync(0xffffffffu, c, o);
        }
        if (tid == 0) { red[0][0] = a; red[1][0] = c; }
    }
    __syncthreads();
    const float mu  = red[0][0] * (1.f / NC);
    const float var = red[1][0] * (1.f / NC) - mu * mu;
    float nv = (v - mu) * rsqrtf(var + 1e-3f) * ln_g[tid] + ln_b[tid];
    nv = 0.5f * nv * (1.f + erff(nv * 0.70710678118654752f));

    sv[tid] = nv;
    __syncthreads();

    const int grp = wid >> 1, comp = wid & 1;
    float part = sv[grp*GC + lane]      * wp[lane * 2 + comp]
               + sv[grp*GC + 32 + lane] * wp[(32 + lane) * 2 + comp];
    #pragma unroll
    for (int o = 16; o > 0; o >>= 1)
        part += __shfl_xor_sync(0xffffffffu, part, o);

    const int pix = p & 1023;
    if (lane == 0) {
        const int yy = pix >> 5, xx = pix & 31;
        float refv = (comp == 0) ? (float)xx : (float)yy;
        spos[grp*2 + comp] = tanhf(part) * 16.f + refv;
    }
    __syncthreads();

    const int b = p >> 10;
    const int g = tid >> 6, c = tid & 63;
    const float p0 = spos[g*2 + 0];
    const float p1 = spos[g*2 + 1];
    const float xqf = p1 + 1.f;
    const float yqf = p0 + 1.f;
    const float x0f = fminf(fmaxf(floorf(xqf), 0.f), 32.f);
    const float y0f = fminf(fmaxf(floorf(yqf), 0.f), 32.f);
    const float ax = fminf(fmaxf(xqf - x0f, 0.f), 1.f);
    const float ay = fminf(fmaxf(yqf - y0f, 0.f), 1.f);
    const int x0 = (int)x0f, y0 = (int)y0f;

    const size_t choff = (size_t)g * GC + c;
    auto fetch = [&](int yy2, int xx2) -> float {
        if (yy2 < 1 || yy2 > 32 || xx2 < 1 || xx2 > 32) return 0.f;
        return x[((size_t)(b*HH + (yy2-1)) * WW + (xx2-1)) * NC + choff];
    };
    float tl = fetch(y0,     x0);
    float tr = fetch(y0,     x0 + 1);
    float bl = fetch(y0 + 1, x0);
    float br = fetch(y0 + 1, x0 + 1);
    float top = tl + ax * (tr - tl);
    float bot = bl + ax * (br - bl);
    g_xs[((size_t)b * NPIX + pix) * NC + choff] = top + ay * (bot - top);
}

// ---------------------------------------------------------------------------
// Launch
// ---------------------------------------------------------------------------
extern "C" void kernel_launch(void* const* d_in, const int* in_sizes, int n_in,
                              void* d_out, int out_size)
{
    const float* x      = (const float*)d_in[0];
    const float* w_q    = (const float*)d_in[1];
    const float* b_q    = (const float*)d_in[2];
    const float* w_off0 = (const float*)d_in[3];
    const float* b_off0 = (const float*)d_in[4];
    const float* ln_g   = (const float*)d_in[5];
    const float* ln_b   = (const float*)d_in[6];
    const float* w_offp = (const float*)d_in[7];
    const float* w_k    = (const float*)d_in[8];
    const float* b_k    = (const float*)d_in[9];
    const float* w_v    = (const float*)d_in[10];
    const float* b_v    = (const float*)d_in[11];
    const float* w_o    = (const float*)d_in[12];
    const float* b_o    = (const float*)d_in[13];
    float* out = (float*)d_out;

    float *pq, *pxs, *pk, *pv, *po;
    cudaGetSymbolAddress((void**)&pq,  g_q);
    cudaGetSymbolAddress((void**)&pxs, g_xs);
    cudaGetSymbolAddress((void**)&pk,  g_k);
    cudaGetSymbolAddress((void**)&pv,  g_v);
    cudaGetSymbolAddress((void**)&po,  g_o);

    cudaFuncSetAttribute(attn_mma_kernel,
                         cudaFuncAttributeMaxDynamicSharedMemorySize, ATTN_SMEM);
    cudaFuncSetAttribute(gemm_mma3_kernel,
                         cudaFuncAttributeMaxDynamicSharedMemorySize, G3_SMEM);
    cudaFuncSetAttribute(gemm_mma_kernel,
                         cudaFuncAttributeMaxDynamicSharedMemorySize, GEMM_SMEM);
    cudaFuncSetAttribute(gemm_kv_kernel,
                         cudaFuncAttributeMaxDynamicSharedMemorySize, GEMM_SMEM);
    cudaFuncSetAttribute(conv_off_kernel,
                         cudaFuncAttributeMaxDynamicSharedMemorySize, CONV_SMEM);

    dim3 ggrid(MTOT / 128, NC / 128);
    dim3 kvgrid(MTOT / 128, NC / 128, 2);
    dim3 agrid(NPIX / 128, HEADS, BB);

    // 1. q = x @ w_q + b_q   (3xTF32 compensated)
    gemm_mma3_kernel<<<ggrid, 256, G3_SMEM>>>(x, w_q, b_q, pq);
    // 2. grouped 3x3 conv on q -> g_t
    conv_off_kernel<<<BB * 8 * GROUPS, 256, CONV_SMEM>>>(w_off0, b_off0);
    // 3. LN + GELU + offset proj + tanh + ref + bilinear sample -> g_xs
    ln_sample_kernel<<<MTOT, NC>>>(ln_g, ln_b, w_offp, x);
    // 4. fused k+v projections (cp.async pipelined tf32 mma)
    gemm_kv_kernel<<<kvgrid, 256, GEMM_SMEM>>>(pxs, w_k, b_k, pk, w_v, b_v, pv);
    // 5. attention (tf32 mma flash, fixed-max softmax) -> g_o
    attn_mma_kernel<<<agrid, 256, ATTN_SMEM>>>();
    // 6. y = o @ w_o + b_o -> d_out
    gemm_mma_kernel<<<ggrid, 256, GEMM_SMEM>>>(po, w_o, b_o, out);
}

// round 11
// speedup vs baseline: 1.3085x; 1.2142x over previous
#include <cuda_runtime.h>
#include <cuda_fp16.h>
#include <math.h>
#include <stdint.h>

// ---------------------------------------------------------------------------
// Problem constants
// ---------------------------------------------------------------------------
#define BB     8
#define HH     32
#define WW     32
#define NC     384
#define GROUPS 6
#define HEADS  12
#define HC     32
#define GC     64
#define NPIX   (HH*WW)          // 1024
#define MTOT   (BB*NPIX)        // 8192
#define NCH    12               // K chunks of 32

// ---------------------------------------------------------------------------
// Scratch (static device globals — no allocation allowed)
// ---------------------------------------------------------------------------
__device__ float g_q  [MTOT*NC];
__device__ float g_t  [MTOT*NC];
__device__ float g_xs [MTOT*NC];
__device__ float g_k  [MTOT*NC];
__device__ float g_v  [MTOT*NC];
__device__ float g_o  [MTOT*NC];

// ---------------------------------------------------------------------------
// mma.sync / packed-f32x2 / cp.async helpers (base sm_103 ISA)
// ---------------------------------------------------------------------------
__device__ __forceinline__ uint32_t f2tf32(float x) {
    uint32_t r;
    asm("cvt.rna.tf32.f32 %0, %1;" : "=r"(r) : "f"(x));
    return r;
}
__device__ __forceinline__ float ex2f(float x) {
    float r;
    asm("ex2.approx.f32 %0, %1;" : "=f"(r) : "f"(x));
    return r;
}
// pack two fp32 -> half2 (lo, hi), round-to-nearest
__device__ __forceinline__ uint32_t f16x2(float lo, float hi) {
    uint32_t r;
    asm("cvt.rn.f16x2.f32 %0, %1, %2;" : "=r"(r) : "f"(hi), "f"(lo));
    return r;
}
__device__ __forceinline__ uint16_t f16b(float x) {
    uint16_t r;
    asm("cvt.rn.f16.f32 %0, %1;" : "=h"(r) : "f"(x));
    return r;
}
__device__ __forceinline__ void mma_tf32(float* c, const uint32_t* a, const uint32_t* b) {
    asm volatile(
        "mma.sync.aligned.m16n8k8.row.col.f32.tf32.tf32.f32 "
        "{%0,%1,%2,%3}, {%4,%5,%6,%7}, {%8,%9}, {%0,%1,%2,%3};"
        : "+f"(c[0]), "+f"(c[1]), "+f"(c[2]), "+f"(c[3])
        : "r"(a[0]), "r"(a[1]), "r"(a[2]), "r"(a[3]), "r"(b[0]), "r"(b[1]));
}
__device__ __forceinline__ void mma_f16(float* c, const uint32_t* a, const uint32_t* b) {
    asm volatile(
        "mma.sync.aligned.m16n8k16.row.col.f32.f16.f16.f32 "
        "{%0,%1,%2,%3}, {%4,%5,%6,%7}, {%8,%9}, {%0,%1,%2,%3};"
        : "+f"(c[0]), "+f"(c[1]), "+f"(c[2]), "+f"(c[3])
        : "r"(a[0]), "r"(a[1]), "r"(a[2]), "r"(a[3]), "r"(b[0]), "r"(b[1]));
}
#define FMA2(d, a, b) \
    asm("fma.rn.f32x2 %0, %1, %2, %0;" : "+l"(d) : "l"(a), "l"(b))
__device__ __forceinline__ uint64_t packf2(float lo, float hi) {
    uint64_t r;
    asm("mov.b64 %0, {%1, %2};" : "=l"(r) : "f"(lo), "f"(hi));
    return r;
}
__device__ __forceinline__ float2 unpackf2(uint64_t v) {
    float2 r;
    asm("mov.b64 {%0, %1}, %2;" : "=f"(r.x), "=f"(r.y) : "l"(v));
    return r;
}
__device__ __forceinline__ void cp16(uint32_t saddr, const void* gptr) {
    asm volatile("cp.async.ca.shared.global [%0], [%1], 16;"
                 :: "r"(saddr), "l"(gptr));
}
#define CP_COMMIT() asm volatile("cp.async.commit_group;" ::: "memory")
#define CP_WAIT0()  asm volatile("cp.async.wait_group 0;"  ::: "memory")

// single dynamic-smem symbol for the whole TU
extern __shared__ uint32_t dynsm[];

// ---------------------------------------------------------------------------
// Pipelined tf32 mma GEMM (R9-proven): 256 thr, warp tile 32x64, cp.async
// double-buffered raw fp32 tiles, cvt at fragment load.
// ---------------------------------------------------------------------------
#define GSA 36
#define GSB 136
#define GEMM_SMEM ((2*128*GSA + 2*32*GSB) * 4)

__device__ __forceinline__ void gemm_body_v3(
    const float* __restrict__ A, const float* __restrict__ W,
    const float* __restrict__ bias, float* __restrict__ C)
{
    float* As = reinterpret_cast<float*>(dynsm);
    float* Bs = As + 2 * 128 * GSA;
    const uint32_t sA = (uint32_t)__cvta_generic_to_shared(As);
    const uint32_t sB = (uint32_t)__cvta_generic_to_shared(Bs);

    const int tid = threadIdx.x, lane = tid & 31, wid = tid >> 5;
    const int wm = wid & 3, wn = wid >> 2;
    const int bm = blockIdx.x * 128, bn = blockIdx.y * 128;
    const int lq = lane >> 2, lr = lane & 3;

    float acc[2][8][4];
    #pragma unroll
    for (int i = 0; i < 2; i++)
        #pragma unroll
        for (int j = 0; j < 8; j++)
            #pragma unroll
            for (int t = 0; t < 4; t++) acc[i][j][t] = 0.f;

    auto stage = [&](int c, int buf) {
        #pragma unroll
        for (int l = 0; l < 4; l++) {
            int idx = tid + l * 256;
            int ra = idx >> 3, ca = idx & 7;
            cp16(sA + (buf * 128 * GSA + ra * GSA + ca * 4) * 4,
                 &A[(size_t)(bm + ra) * NC + c * 32 + ca * 4]);
            int rb = idx >> 5, cb = idx & 31;
            cp16(sB + (buf * 32 * GSB + rb * GSB + cb * 4) * 4,
                 &W[(size_t)(c * 32 + rb) * NC + bn + cb * 4]);
        }
        CP_COMMIT();
    };

    stage(0, 0);
    CP_WAIT0();
    __syncthreads();

    for (int c = 0; c < NCH; c++) {
        const int buf = c & 1;
        const bool more = (c + 1 < NCH);
        if (more) stage(c + 1, buf ^ 1);

        const float* Ab = As + buf * 128 * GSA;
        const float* Bb = Bs + buf * 32 * GSB;
        #pragma unroll
        for (int ks = 0; ks < 4; ks++) {
            const int k0 = ks * 8;
            uint32_t af[2][4];
            #pragma unroll
            for (int i = 0; i < 2; i++) {
                const int rb = wm * 32 + i * 16;
                af[i][0] = f2tf32(Ab[(rb +     lq) * GSA + k0 +     lr]);
                af[i][1] = f2tf32(Ab[(rb + 8 + lq) * GSA + k0 +     lr]);
                af[i][2] = f2tf32(Ab[(rb +     lq) * GSA + k0 + 4 + lr]);
                af[i][3] = f2tf32(Ab[(rb + 8 + lq) * GSA + k0 + 4 + lr]);
            }
            #pragma unroll
            for (int j = 0; j < 8; j++) {
                uint32_t bf[2];
                const int col = wn * 64 + j * 8 + lq;
                bf[0] = f2tf32(Bb[(k0 +     lr) * GSB + col]);
                bf[1] = f2tf32(Bb[(k0 + 4 + lr) * GSB + col]);
                mma_tf32(acc[0][j], af[0], bf);
                mma_tf32(acc[1][j], af[1], bf);
            }
        }
        if (more) CP_WAIT0();
        __syncthreads();
    }

    #pragma unroll
    for (int j = 0; j < 8; j++) {
        const int col = bn + wn * 64 + j * 8 + lr * 2;
        const float b0 = bias[col], b1 = bias[col + 1];
        #pragma unroll
        for (int i = 0; i < 2; i++) {
            const int r0 = bm + wm * 32 + i * 16 + lq;
            *reinterpret_cast<float2*>(&C[(size_t)r0 * NC + col]) =
                make_float2(acc[i][j][0] + b0, acc[i][j][1] + b1);
            *reinterpret_cast<float2*>(&C[(size_t)(r0 + 8) * NC + col]) =
                make_float2(acc[i][j][2] + b0, acc[i][j][3] + b1);
        }
    }
}

__global__ __launch_bounds__(256) void gemm_mma_kernel(
    const float* __restrict__ A, const float* __restrict__ W,
    const float* __restrict__ bias, float* __restrict__ C)
{
    gemm_body_v3(A, W, bias, C);
}

__global__ __launch_bounds__(256) void gemm_kv_kernel(
    const float* __restrict__ A,
    const float* __restrict__ Wk, const float* __restrict__ bk, float* __restrict__ K,
    const float* __restrict__ Wv, const float* __restrict__ bv, float* __restrict__ V)
{
    if (blockIdx.z == 0)
        gemm_body_v3(A, Wk, bk, K);
    else
        gemm_body_v3(A, Wv, bv, V);
}

// ---------------------------------------------------------------------------
// 3xTF32 compensated GEMM (near-fp32) — q projection only (R6/R9-proven).
// ---------------------------------------------------------------------------
#define G3_SMEM ((128*GSA*2 + 32*GSB*2) * 4)

__global__ __launch_bounds__(256) void gemm_mma3_kernel(
    const float* __restrict__ A, const float* __restrict__ W,
    const float* __restrict__ bias, float* __restrict__ C)
{
    uint32_t* s3 = dynsm;
    uint32_t* AsH = s3;
    uint32_t* AsL = s3 + 128 * GSA;
    uint32_t* BsH = s3 + 2 * 128 * GSA;
    uint32_t* BsL = BsH + 32 * GSB;

    const int tid = threadIdx.x, lane = tid & 31, wid = tid >> 5;
    const int wm = wid & 3, wn = wid >> 2;
    const int bm = blockIdx.x * 128, bn = blockIdx.y * 128;
    const int lq = lane >> 2, lr = lane & 3;

    float acc[2][8][4];
    #pragma unroll
    for (int i = 0; i < 2; i++)
        #pragma unroll
        for (int j = 0; j < 8; j++)
            #pragma unroll
            for (int t = 0; t < 4; t++) acc[i][j][t] = 0.f;

    for (int c = 0; c < NCH; c++) {
        #pragma unroll
        for (int l = 0; l < 4; l++) {
            int idx = tid + l * 256;
            int row = idx >> 3, c4 = idx & 7;
            float4 v = *reinterpret_cast<const float4*>(
                &A[(size_t)(bm + row) * NC + c * 32 + c4 * 4]);
            uint32_t* dh = &AsH[row * GSA + c4 * 4];
            uint32_t* dl = &AsL[row * GSA + c4 * 4];
            uint32_t h;
            h = f2tf32(v.x); dh[0] = h; dl[0] = f2tf32(v.x - __uint_as_float(h));
            h = f2tf32(v.y); dh[1] = h; dl[1] = f2tf32(v.y - __uint_as_float(h));
            h = f2tf32(v.z); dh[2] = h; dl[2] = f2tf32(v.z - __uint_as_float(h));
            h = f2tf32(v.w); dh[3] = h; dl[3] = f2tf32(v.w - __uint_as_float(h));
        }
        #pragma unroll
        for (int l = 0; l < 4; l++) {
            int idx = tid + l * 256;
            int row = idx >> 5, c4 = idx & 31;
            float4 v = *reinterpret_cast<const float4*>(
                &W[(size_t)(c * 32 + row) * NC + bn + c4 * 4]);
            uint32_t* dh = &BsH[row * GSB + c4 * 4];
            uint32_t* dl = &BsL[row * GSB + c4 * 4];
            uint32_t h;
            h = f2tf32(v.x); dh[0] = h; dl[0] = f2tf32(v.x - __uint_as_float(h));
            h = f2tf32(v.y); dh[1] = h; dl[1] = f2tf32(v.y - __uint_as_float(h));
            h = f2tf32(v.z); dh[2] = h; dl[2] = f2tf32(v.z - __uint_as_float(h));
            h = f2tf32(v.w); dh[3] = h; dl[3] = f2tf32(v.w - __uint_as_float(h));
        }
        __syncthreads();
        #pragma unroll
        for (int ks = 0; ks < 4; ks++) {
            const int k0 = ks * 8;
            uint32_t afh[2][4], afl[2][4];
            #pragma unroll
            for (int i = 0; i < 2; i++) {
                const int rb = wm * 32 + i * 16;
                afh[i][0] = AsH[(rb +     lq) * GSA + k0 +     lr];
                afh[i][1] = AsH[(rb + 8 + lq) * GSA + k0 +     lr];
                afh[i][2] = AsH[(rb +     lq) * GSA + k0 + 4 + lr];
                afh[i][3] = AsH[(rb + 8 + lq) * GSA + k0 + 4 + lr];
                afl[i][0] = AsL[(rb +     lq) * GSA + k0 +     lr];
                afl[i][1] = AsL[(rb + 8 + lq) * GSA + k0 +     lr];
                afl[i][2] = AsL[(rb +     lq) * GSA + k0 + 4 + lr];
                afl[i][3] = AsL[(rb + 8 + lq) * GSA + k0 + 4 + lr];
            }
            #pragma unroll
            for (int j = 0; j < 8; j++) {
                uint32_t bfh[2], bfl[2];
                const int col = wn * 64 + j * 8 + lq;
                bfh[0] = BsH[(k0 +     lr) * GSB + col];
                bfh[1] = BsH[(k0 + 4 + lr) * GSB + col];
                bfl[0] = BsL[(k0 +     lr) * GSB + col];
                bfl[1] = BsL[(k0 + 4 + lr) * GSB + col];
                #pragma unroll
                for (int i = 0; i < 2; i++) {
                    mma_tf32(acc[i][j], afl[i], bfh);
                    mma_tf32(acc[i][j], afh[i], bfl);
                    mma_tf32(acc[i][j], afh[i], bfh);
                }
            }
        }
        __syncthreads();
    }
    #pragma unroll
    for (int j = 0; j < 8; j++) {
        const int col = bn + wn * 64 + j * 8 + lr * 2;
        const float b0 = bias[col], b1 = bias[col + 1];
        #pragma unroll
        for (int i = 0; i < 2; i++) {
            const int r0 = bm + wm * 32 + i * 16 + lq;
            *reinterpret_cast<float2*>(&C[(size_t)r0 * NC + col]) =
                make_float2(acc[i][j][0] + b0, acc[i][j][1] + b1);
            *reinterpret_cast<float2*>(&C[(size_t)(r0 + 8) * NC + col]) =
                make_float2(acc[i][j][2] + b0, acc[i][j][3] + b1);
        }
    }
}

// ---------------------------------------------------------------------------
// Flash attention v4: fp16 m16n8k16 mma, fixed-max softmax, P stays in
// registers (C-frag of S == A-frag of P after f16x2 pack), double-buffered
// fp16 K/V with register prefetch. smem: K [2][64][40h], Vt [2][32][72h],
// Q staged fp16 [128][40h] overlaid on the K/V region before the mainloop.
// ---------------------------------------------------------------------------
#define KW  20      // K row stride in u32 words (40 halves)
#define VTW 36      // Vt row stride in u32 words (72 halves)
#define ATTN_SMEM (2*64*KW*4 + 2*32*VTW*4)   // 10240 + 9216 = 19456 B

__global__ __launch_bounds__(256) void attn_mma_kernel()
{
    uint32_t* Khw = dynsm;                        // [2][64*KW]
    uint32_t* Vtw = dynsm + 2 * 64 * KW;          // [2][32*VTW]

    const int tid = threadIdx.x, lane = tid & 31, wid = tid >> 5;
    const int lq = lane >> 2, lr = lane & 3;
    const int qt = blockIdx.x, h = blockIdx.y, b = blockIdx.z;
    const int q0 = qt * 128;

    // --- stage Q fp16 (scale*log2e folded) into smem overlay, grab frags ---
    const float qscale = 0.17677669529663689f * 1.4426950408889634f;
    uint32_t* Qw = dynsm;                         // [128][KW] overlay
    #pragma unroll
    for (int l = 0; l < 4; l++) {
        int idx = tid + l * 256;
        int row = idx >> 3, c4 = idx & 7;
        float4 v = *reinterpret_cast<const float4*>(
            &g_q[((size_t)b * NPIX + q0 + row) * NC + h * HC + c4 * 4]);
        Qw[row * KW + c4 * 2 + 0] = f16x2(v.x * qscale, v.y * qscale);
        Qw[row * KW + c4 * 2 + 1] = f16x2(v.z * qscale, v.w * qscale);
    }
    __syncthreads();
    uint32_t qf[2][4];
    {
        const int rb = wid * 16;
        #pragma unroll
        for (int ks = 0; ks < 2; ks++) {
            qf[ks][0] = Qw[(rb +     lq) * KW + lr +     8 * ks];
            qf[ks][1] = Qw[(rb + 8 + lq) * KW + lr +     8 * ks];
            qf[ks][2] = Qw[(rb +     lq) * KW + lr + 4 + 8 * ks];
            qf[ks][3] = Qw[(rb + 8 + lq) * KW + lr + 4 + 8 * ks];
        }
    }
    __syncthreads();   // overlay region now free for K/V buffers

    float o[4][4];
    #pragma unroll
    for (int j = 0; j < 4; j++)
        #pragma unroll
        for (int t = 0; t < 4; t++) o[j][t] = 0.f;
    float l0 = 0.f, l1 = 0.f;

    // per-thread tile slice: 8 K values + 8 V values (2 float4 each)
    auto ldtile = [&](int kt, float4* rk, float4* rv) {
        #pragma unroll
        for (int l = 0; l < 2; l++) {
            int idx = tid + l * 256;
            int key = idx >> 3, c4 = idx & 7;
            size_t base = ((size_t)b * NPIX + kt + key) * NC + h * HC + c4 * 4;
            rk[l] = *reinterpret_cast<const float4*>(&g_k[base]);
            rv[l] = *reinterpret_cast<const float4*>(&g_v[base]);
        }
    };
    auto sttile = [&](int buf, const float4* rk, const float4* rv) {
        uint32_t* K = Khw + buf * 64 * KW;
        uint16_t* Vt = reinterpret_cast<uint16_t*>(Vtw + buf * 32 * VTW);
        #pragma unroll
        for (int l = 0; l < 2; l++) {
            int idx = tid + l * 256;
            int key = idx >> 3, c4 = idx & 7;
            K[key * KW + c4 * 2 + 0] = f16x2(rk[l].x, rk[l].y);
            K[key * KW + c4 * 2 + 1] = f16x2(rk[l].z, rk[l].w);
            Vt[(c4 * 4 + 0) * (2 * VTW) + key] = f16b(rv[l].x);
            Vt[(c4 * 4 + 1) * (2 * VTW) + key] = f16b(rv[l].y);
            Vt[(c4 * 4 + 2) * (2 * VTW) + key] = f16b(rv[l].z);
            Vt[(c4 * 4 + 3) * (2 * VTW) + key] = f16b(rv[l].w);
        }
    };

    {
        float4 rk[2], rv[2];
        ldtile(0, rk, rv);
        sttile(0, rk, rv);
    }
    __syncthreads();

    for (int it = 0; it < 16; it++) {
        const int buf = it & 1;
        const bool more = (it < 15);
        float4 rk[2], rv[2];
        if (more) ldtile((it + 1) * 64, rk, rv);

        const uint32_t* K = Khw + buf * 64 * KW;
        const uint32_t* V = Vtw + buf * 32 * VTW;

        // mma1: S(16x64) = Q @ K^T (log2 domain), fp16 k16
        float s[8][4];
        #pragma unroll
        for (int j = 0; j < 8; j++)
            #pragma unroll
            for (int t = 0; t < 4; t++) s[j][t] = 0.f;
        #pragma unroll
        for (int ks = 0; ks < 2; ks++) {
            #pragma unroll
            for (int j = 0; j < 8; j++) {
                uint32_t bf[2];
                const int col = j * 8 + lq;
                bf[0] = K[col * KW + lr +     8 * ks];
                bf[1] = K[col * KW + lr + 4 + 8 * ks];
                mma_f16(s[j], qf[ks], bf);
            }
        }

        // fixed-max softmax numerator, kept in registers
        #pragma unroll
        for (int j = 0; j < 8; j++) {
            s[j][0] = ex2f(s[j][0]);
            s[j][1] = ex2f(s[j][1]);
            s[j][2] = ex2f(s[j][2]);
            s[j][3] = ex2f(s[j][3]);
            l0 += s[j][0] + s[j][1];
            l1 += s[j][2] + s[j][3];
        }

        if (more) sttile(buf ^ 1, rk, rv);   // overlaps with mma2 below

        // mma2: O(16x32) += P(16x64) @ V(64x32); P = repacked S fragments
        #pragma unroll
        for (int ks = 0; ks < 4; ks++) {
            uint32_t ap[4];
            ap[0] = f16x2(s[2*ks    ][0], s[2*ks    ][1]);
            ap[1] = f16x2(s[2*ks    ][2], s[2*ks    ][3]);
            ap[2] = f16x2(s[2*ks + 1][0], s[2*ks + 1][1]);
            ap[3] = f16x2(s[2*ks + 1][2], s[2*ks + 1][3]);
            #pragma unroll
            for (int j = 0; j < 4; j++) {
                uint32_t bf[2];
                const int n = j * 8 + lq;
                bf[0] = V[n * VTW + lr +     8 * ks];
                bf[1] = V[n * VTW + lr + 4 + 8 * ks];
                mma_f16(o[j], ap, bf);
            }
        }
        __syncthreads();
    }

    // deferred row-sum reduction
    l0 += __shfl_xor_sync(0xffffffffu, l0, 1);
    l0 += __shfl_xor_sync(0xffffffffu, l0, 2);
    l1 += __shfl_xor_sync(0xffffffffu, l1, 1);
    l1 += __shfl_xor_sync(0xffffffffu, l1, 2);
    const float il0 = 1.f / l0, il1 = 1.f / l1;
    const int rg = q0 + wid * 16 + lq;
    #pragma unroll
    for (int j = 0; j < 4; j++) {
        const int col = h * HC + j * 8 + lr * 2;
        *reinterpret_cast<float2*>(&g_o[((size_t)b * NPIX + rg) * NC + col]) =
            make_float2(o[j][0] * il0, o[j][1] * il0);
        *reinterpret_cast<float2*>(&g_o[((size_t)b * NPIX + rg + 8) * NC + col]) =
            make_float2(o[j][2] * il1, o[j][3] * il1);
    }
}

// ---------------------------------------------------------------------------
// Grouped 3x3 conv (packed fma.rn.f32x2, bit-exact fp32) — unchanged.
// ---------------------------------------------------------------------------
#define CONV_SMEM (64 * 6 * 36 * 4)

__global__ __launch_bounds__(256) void conv_off_kernel(
    const float* __restrict__ W, const float* __restrict__ bias)
{
    float* qs = reinterpret_cast<float*>(dynsm);   // [64 ic][6 r][36 x]
    const int bid = blockIdx.x;
    const int g  = bid % GROUPS;
    const int yt = (bid / GROUPS) & 7;
    const int b  = bid / (GROUPS * 8);
    const int y0 = yt * 4;
    const int tid = threadIdx.x;

    for (int i = tid; i < 64 * 6 * 34; i += 256) {
        int c  = i & 63;
        int xx = (i >> 6) % 34;
        int r  = i / (64 * 34);
        int yy = y0 + r - 1;
        float v = 0.f;
        if (xx >= 1 && xx <= 32 && yy >= 0 && yy < HH)
            v = g_q[((size_t)(b*HH + yy)*WW + (xx-1)) * NC + g*GC + c];
        qs[(c * 6 + r) * 36 + xx] = v;
    }
    __syncthreads();

    const int ty = tid >> 6;
    const int x0 = ((tid >> 4) & 3) * 8;
    const int oc = (tid & 15) * 4;
    const int y  = y0 + ty;

    uint64_t acc01[8], acc23[8];
    {
        float4 bv = *reinterpret_cast<const float4*>(&bias[g*GC + oc]);
        uint64_t b01 = packf2(bv.x, bv.y), b23 = packf2(bv.z, bv.w);
        #pragma unroll
        for (int xi = 0; xi < 8; xi++) { acc01[xi] = b01; acc23[xi] = b23; }
    }

    #pragma unroll
    for (int dy = 0; dy < 3; dy++) {
        const int r = ty + dy;
        #pragma unroll 2
        for (int ic = 0; ic < GC; ic++) {
            const float* qrow = &qs[(ic * 6 + r) * 36 + x0];
            uint64_t qp[10];
            #pragma unroll
            for (int j = 0; j < 10; j++) {
                float qv = qrow[j];
                qp[j] = packf2(qv, qv);
            }
            const uint64_t* wp0 = reinterpret_cast<const uint64_t*>(
                &W[(size_t)((dy*3 + 0) * GC + ic) * NC + g*GC + oc]);
            const uint64_t* wp1 = reinterpret_cast<const uint64_t*>(
                &W[(size_t)((dy*3 + 1) * GC + ic) * NC + g*GC + oc]);
            const uint64_t* wp2 = reinterpret_cast<const uint64_t*>(
                &W[(size_t)((dy*3 + 2) * GC + ic) * NC + g*GC + oc]);
            const uint64_t w0a = wp0[0], w0b = wp0[1];
            const uint64_t w1a = wp1[0], w1b = wp1[1];
            const uint64_t w2a = wp2[0], w2b = wp2[1];
            #pragma unroll
            for (int xi = 0; xi < 8; xi++) {
                FMA2(acc01[xi], w0a, qp[xi]);
                FMA2(acc23[xi], w0b, qp[xi]);
                FMA2(acc01[xi], w1a, qp[xi + 1]);
                FMA2(acc23[xi], w1b, qp[xi + 1]);
                FMA2(acc01[xi], w2a, qp[xi + 2]);
                FMA2(acc23[xi], w2b, qp[xi + 2]);
            }
        }
    }

    #pragma unroll
    for (int xi = 0; xi < 8; xi++) {
        float2 a = unpackf2(acc01[xi]);
        float2 c = unpackf2(acc23[xi]);
        float4 o = make_float4(a.x, a.y, c.x, c.y);
        *reinterpret_cast<float4*>(
            &g_t[((size_t)(b*HH + y)*WW + x0 + xi) * NC + g*GC + oc]) = o;
    }
}

// ---------------------------------------------------------------------------
// Fused: LayerNorm + erf-GELU + offset proj + tanh*range + ref grid + sample.
// ---------------------------------------------------------------------------
__global__ __launch_bounds__(384) void ln_sample_kernel(
    const float* __restrict__ ln_g, const float* __restrict__ ln_b,
    const float* __restrict__ wp, const float* __restrict__ x)
{
    const int p   = blockIdx.x;
    const int tid = threadIdx.x;
    const int wid  = tid >> 5;
    const int lane = tid & 31;

    float v = g_t[(size_t)p * NC + tid];

    __shared__ float red[2][12];
    __shared__ float sv[NC];
    __shared__ float spos[12];

    float s = v, sq = v * v;
    #pragma unroll
    for (int o = 16; o > 0; o >>= 1) {
        s  += __shfl_xor_sync(0xffffffffu, s,  o);
        sq += __shfl_xor_sync(0xffffffffu, sq, o);
    }
    if (lane == 0) { red[0][wid] = s; red[1][wid] = sq; }
    __syncthreads();
    if (tid < 32) {
        float a = (tid < 12) ? red[0][tid] : 0.f;
        float c = (tid < 12) ? red[1][tid] : 0.f;
        #pragma unroll
        for (int o = 8; o > 0; o >>= 1) {
            a += __shfl_xor_sync(0xffffffffu, a, o);
            c += __shfl_xor_sync(0xffffffffu, c, o);
        }
        if (tid == 0) { red[0][0] = a; red[1][0] = c; }
    }
    __syncthreads();
    const float mu  = red[0][0] * (1.f / NC);
    const float var = red[1][0] * (1.f / NC) - mu * mu;
    float nv = (v - mu) * rsqrtf(var + 1e-3f) * ln_g[tid] + ln_b[tid];
    nv = 0.5f * nv * (1.f + erff(nv * 0.70710678118654752f));

    sv[tid] = nv;
    __syncthreads();

    const int grp = wid >> 1, comp = wid & 1;
    float part = sv[grp*GC + lane]      * wp[lane * 2 + comp]
               + sv[grp*GC + 32 + lane] * wp[(32 + lane) * 2 + comp];
    #pragma unroll
    for (int o = 16; o > 0; o >>= 1)
        part += __shfl_xor_sync(0xffffffffu, part, o);

    const int pix = p & 1023;
    if (lane == 0) {
        const int yy = pix >> 5, xx = pix & 31;
        float refv = (comp == 0) ? (float)xx : (float)yy;
        spos[grp*2 + comp] = tanhf(part) * 16.f + refv;
    }
    __syncthreads();

    const int b = p >> 10;
    const int g = tid >> 6, c = tid & 63;
    const float p0 = spos[g*2 + 0];
    const float p1 = spos[g*2 + 1];
    const float xqf = p1 + 1.f;
    const float yqf = p0 + 1.f;
    const float x0f = fminf(fmaxf(floorf(xqf), 0.f), 32.f);
    const float y0f = fminf(fmaxf(floorf(yqf), 0.f), 32.f);
    const float ax = fminf(fmaxf(xqf - x0f, 0.f), 1.f);
    const float ay = fminf(fmaxf(yqf - y0f, 0.f), 1.f);
    const int x0 = (int)x0f, y0 = (int)y0f;

    const size_t choff = (size_t)g * GC + c;
    auto fetch = [&](int yy2, int xx2) -> float {
        if (yy2 < 1 || yy2 > 32 || xx2 < 1 || xx2 > 32) return 0.f;
        return x[((size_t)(b*HH + (yy2-1)) * WW + (xx2-1)) * NC + choff];
    };
    float tl = fetch(y0,     x0);
    float tr = fetch(y0,     x0 + 1);
    float bl = fetch(y0 + 1, x0);
    float br = fetch(y0 + 1, x0 + 1);
    float top = tl + ax * (tr - tl);
    float bot = bl + ax * (br - bl);
    g_xs[((size_t)b * NPIX + pix) * NC + choff] = top + ay * (bot - top);
}

// ---------------------------------------------------------------------------
// Launch
// ---------------------------------------------------------------------------
extern "C" void kernel_launch(void* const* d_in, const int* in_sizes, int n_in,
                              void* d_out, int out_size)
{
    const float* x      = (const float*)d_in[0];
    const float* w_q    = (const float*)d_in[1];
    const float* b_q    = (const float*)d_in[2];
    const float* w_off0 = (const float*)d_in[3];
    const float* b_off0 = (const float*)d_in[4];
    const float* ln_g   = (const float*)d_in[5];
    const float* ln_b   = (const float*)d_in[6];
    const float* w_offp = (const float*)d_in[7];
    const float* w_k    = (const float*)d_in[8];
    const float* b_k    = (const float*)d_in[9];
    const float* w_v    = (const float*)d_in[10];
    const float* b_v    = (const float*)d_in[11];
    const float* w_o    = (const float*)d_in[12];
    const float* b_o    = (const float*)d_in[13];
    float* out = (float*)d_out;

    float *pq, *pxs, *pk, *pv, *po;
    cudaGetSymbolAddress((void**)&pq,  g_q);
    cudaGetSymbolAddress((void**)&pxs, g_xs);
    cudaGetSymbolAddress((void**)&pk,  g_k);
    cudaGetSymbolAddress((void**)&pv,  g_v);
    cudaGetSymbolAddress((void**)&po,  g_o);

    cudaFuncSetAttribute(attn_mma_kernel,
                         cudaFuncAttributeMaxDynamicSharedMemorySize, ATTN_SMEM);
    cudaFuncSetAttribute(gemm_mma3_kernel,
                         cudaFuncAttributeMaxDynamicSharedMemorySize, G3_SMEM);
    cudaFuncSetAttribute(gemm_mma_kernel,
                         cudaFuncAttributeMaxDynamicSharedMemorySize, GEMM_SMEM);
    cudaFuncSetAttribute(gemm_kv_kernel,
                         cudaFuncAttributeMaxDynamicSharedMemorySize, GEMM_SMEM);
    cudaFuncSetAttribute(conv_off_kernel,
                         cudaFuncAttributeMaxDynamicSharedMemorySize, CONV_SMEM);

    dim3 ggrid(MTOT / 128, NC / 128);
    dim3 kvgrid(MTOT / 128, NC / 128, 2);
    dim3 agrid(NPIX / 128, HEADS, BB);

    // 1. q = x @ w_q + b_q   (3xTF32 compensated)
    gemm_mma3_kernel<<<ggrid, 256, G3_SMEM>>>(x, w_q, b_q, pq);
    // 2. grouped 3x3 conv on q -> g_t
    conv_off_kernel<<<BB * 8 * GROUPS, 256, CONV_SMEM>>>(w_off0, b_off0);
    // 3. LN + GELU + offset proj + tanh + ref + bilinear sample -> g_xs
    ln_sample_kernel<<<MTOT, NC>>>(ln_g, ln_b, w_offp, x);
    // 4. fused k+v projections (cp.async pipelined tf32 mma)
    gemm_kv_kernel<<<kvgrid, 256, GEMM_SMEM>>>(pxs, w_k, b_k, pk, w_v, b_v, pv);
    // 5. attention (fp16 m16n8k16 flash, register-resident P) -> g_o
    attn_mma_kernel<<<agrid, 256, ATTN_SMEM>>>();
    // 6. y = o @ w_o + b_o -> d_out
    gemm_mma_kernel<<<ggrid, 256, GEMM_SMEM>>>(po, w_o, b_o, out);
}